// round 2
// baseline (speedup 1.0000x reference)
#include <cuda_runtime.h>
#include <math.h>

// Problem dims (fixed by setup_inputs)
#define BDIM 2
#define NTOT 1024
#define PLEN 768
#define LLEN 256
#define KDIM 128
#define HDIM 32

constexpr int TM    = 64;    // edges per tile
constexpr int PITCH = 132;   // smem row pitch (floats): 528B, 16B-aligned, conflict-free f4 column loads
constexpr int NT_LL = BDIM * LLEN * (LLEN / TM);   // 2048
constexpr int NT_LP = BDIM * PLEN * (LLEN / TM);   // 6144
constexpr int NTILES = NT_LL + NT_LP;              // 8192

// shared memory layout (float offsets)
constexpr int OFF_OW1  = 0;                        // [128][128]
constexpr int OFF_OW2  = OFF_OW1 + KDIM * KDIM;    // 16384  [128][32]
constexpr int OFF_VW2  = OFF_OW2 + KDIM * HDIM;    // 20480  [128][32]
constexpr int OFF_VW1  = OFF_VW2 + KDIM * HDIM;    // 24576  [3][128]
constexpr int OFF_VB1  = OFF_VW1 + 3 * KDIM;       // 24960
constexpr int OFF_OB1  = OFF_VB1 + KDIM;           // 25088
constexpr int OFF_MEAN = OFF_OB1 + KDIM;           // 25216
constexpr int OFF_ISTD = OFF_MEAN + KDIM;          // 25344
constexpr int OFF_COEF = OFF_ISTD + KDIM;          // 25472
constexpr int OFF_B2   = OFF_COEF + KDIM;          // 25600  ob2+vb2
constexpr int OFF_X0   = OFF_B2 + HDIM;            // 25632
constexpr int OFF_DLM  = OFF_X0 + TM;              // 25696  [64][3]
constexpr int OFF_G    = OFF_DLM + TM * 3;         // 25888  (16B aligned) [64][PITCH], reused as H1
constexpr int OFF_V1   = OFF_G + TM * PITCH;       // 34336
constexpr int OFF_V2   = OFF_V1 + TM * PITCH;      // 42784
constexpr int SMEM_FLOATS = OFF_V2 + TM * PITCH;   // 51232
constexpr int SMEM_BYTES  = SMEM_FLOATS * 4;       // 204928

__device__ __forceinline__ float gelu_exact(float x) {
    return 0.5f * x * (1.0f + erff(x * 0.70710678118654752f));
}

// Zero-fill the protein-protein quadrant: out[b,h,i>=L,j>=L]
__global__ void zero_pp_kernel(float* __restrict__ out) {
    const int q = PLEN / 4;  // 192 float4 per row segment
    size_t idx = (size_t)blockIdx.x * blockDim.x + threadIdx.x;
    size_t total = (size_t)BDIM * HDIM * PLEN * q;
    if (idx >= total) return;
    int jq = (int)(idx % q);
    size_t r = idx / q;
    int ip = (int)(r % PLEN);
    size_t bh = r / PLEN;
    size_t addr = (bh * NTOT + (LLEN + ip)) * NTOT + LLEN + 4 * jq;
    *reinterpret_cast<float4*>(out + addr) = make_float4(0.f, 0.f, 0.f, 0.f);
}

__global__ __launch_bounds__(256, 1)
void fused_distbias_kernel(
    const float* __restrict__ pos,       // [B,N,3]
    const int*   __restrict__ etype,     // [B,N,N]
    const float* __restrict__ mw,        // [E,1]
    const float* __restrict__ bw,        // [E,1]
    const float* __restrict__ means,     // [K]
    const float* __restrict__ stds,      // [K]
    const float* __restrict__ ow1,       // [K,K]
    const float* __restrict__ ob1,       // [K]
    const float* __restrict__ ow2,       // [K,H]
    const float* __restrict__ ob2,       // [H]
    const float* __restrict__ vw1,       // [3,128]
    const float* __restrict__ vb1,       // [128]
    const float* __restrict__ vw2,       // [128,H]
    const float* __restrict__ vb2,       // [H]
    float* __restrict__ out)             // [B,H,N,N]
{
    extern __shared__ float sm[];
    const int tid = threadIdx.x;

    // ---- Stage weights into shared memory (once per block) ----
    for (int i = tid; i < KDIM * KDIM / 4; i += 256)
        reinterpret_cast<float4*>(sm + OFF_OW1)[i] = reinterpret_cast<const float4*>(ow1)[i];
    for (int i = tid; i < KDIM * HDIM / 4; i += 256) {
        reinterpret_cast<float4*>(sm + OFF_OW2)[i] = reinterpret_cast<const float4*>(ow2)[i];
        reinterpret_cast<float4*>(sm + OFF_VW2)[i] = reinterpret_cast<const float4*>(vw2)[i];
    }
    for (int i = tid; i < 3 * KDIM; i += 256) sm[OFF_VW1 + i] = vw1[i];
    for (int i = tid; i < KDIM; i += 256) {
        sm[OFF_VB1 + i] = vb1[i];
        sm[OFF_OB1 + i] = ob1[i];
        float s  = fabsf(stds[i]) + 1e-5f;
        float is = 1.0f / s;
        sm[OFF_MEAN + i] = means[i];
        sm[OFF_ISTD + i] = is;
        sm[OFF_COEF + i] = is * (1.0f / sqrtf(2.0f * 3.14159f));  // matches PI=3.14159 in reference
    }
    if (tid < HDIM) sm[OFF_B2 + tid] = ob2[tid] + vb2[tid];
    __syncthreads();

    for (int t = blockIdx.x; t < NTILES; t += gridDim.x) {
        int b, rowi, j0, isLP;
        if (t < NT_LL) {
            isLP = 0;
            b = t >> 10;                 // 1024 tiles per b
            int r = t & 1023;
            rowi = r >> 2;               // ligand row i (< L)
            j0 = (r & 3) << 6;
        } else {
            isLP = 1;
            int u = t - NT_LL;
            b = u / 3072;                // 3072 tiles per b
            int r = u % 3072;
            rowi = LLEN + (r >> 2);      // protein row (L + p)
            j0 = (r & 3) << 6;
        }

        // ---- Edge metadata: dlm, x0 = mul*dist + bias ----
        if (tid < TM) {
            int j = j0 + tid;            // ligand column index (< L)
            const float* pj = pos + ((size_t)b * NTOT + j) * 3;
            const float* pi = pos + ((size_t)b * NTOT + rowi) * 3;
            float d0 = pj[0] - pi[0];
            float d1 = pj[1] - pi[1];
            float d2 = pj[2] - pi[2];
            float d = 1.0f / (d0 * d0 + d1 * d1 + d2 * d2 + 1.0f);
            int e = etype[((size_t)b * NTOT + rowi) * NTOT + j];
            sm[OFF_X0 + tid] = mw[e] * d + bw[e];
            sm[OFF_DLM + tid * 3 + 0] = d0;
            sm[OFF_DLM + tid * 3 + 1] = d1;
            sm[OFF_DLM + tid * 3 + 2] = d2;
        }
        __syncthreads();

        // ---- Gaussian features + vector-MLP hidden layer(s) ----
        for (int idx = tid; idx < TM * KDIM; idx += 256) {
            int m = idx >> 7, k = idx & 127;
            float tt = (sm[OFF_X0 + m] - sm[OFF_MEAN + k]) * sm[OFF_ISTD + k];
            sm[OFF_G + m * PITCH + k] = __expf(-0.5f * tt * tt) * sm[OFF_COEF + k];
            float s = sm[OFF_DLM + m * 3 + 0] * sm[OFF_VW1 + k]
                    + sm[OFF_DLM + m * 3 + 1] * sm[OFF_VW1 + KDIM + k]
                    + sm[OFF_DLM + m * 3 + 2] * sm[OFF_VW1 + 2 * KDIM + k]
                    + sm[OFF_VB1 + k];
            sm[OFF_V1 + m * PITCH + k] = gelu_exact(s);
            if (isLP)  // MLP(-dlm): 2*vb1 - s negates the dot product
                sm[OFF_V2 + m * PITCH + k] = gelu_exact(2.0f * sm[OFF_VB1 + k] - s);
        }
        __syncthreads();

        // ---- Stage 1 GEMM: H1 = gelu(G[64,128] @ ow1[128,128] + ob1) ----
        {
            const int nt = tid & 31;      // 4 output cols: 4*nt..
            const int mt = tid >> 5;      // 8 output rows: 8*mt..
            float acc[8][4];
            {
                float4 bb = *reinterpret_cast<float4*>(sm + OFF_OB1 + 4 * nt);
                #pragma unroll
                for (int r = 0; r < 8; r++) {
                    acc[r][0] = bb.x; acc[r][1] = bb.y; acc[r][2] = bb.z; acc[r][3] = bb.w;
                }
            }
            #pragma unroll 4
            for (int k = 0; k < KDIM; k++) {
                float4 w = *reinterpret_cast<float4*>(sm + OFF_OW1 + k * KDIM + 4 * nt);
                #pragma unroll
                for (int r = 0; r < 8; r++) {
                    float g = sm[OFF_G + (mt * 8 + r) * PITCH + k];  // warp-broadcast
                    acc[r][0] += g * w.x;
                    acc[r][1] += g * w.y;
                    acc[r][2] += g * w.z;
                    acc[r][3] += g * w.w;
                }
            }
            __syncthreads();  // all G reads complete before overwrite
            #pragma unroll
            for (int r = 0; r < 8; r++) {
                float4 o;
                o.x = gelu_exact(acc[r][0]);
                o.y = gelu_exact(acc[r][1]);
                o.z = gelu_exact(acc[r][2]);
                o.w = gelu_exact(acc[r][3]);
                *reinterpret_cast<float4*>(sm + OFF_G + (mt * 8 + r) * PITCH + 4 * nt) = o;
            }
        }
        __syncthreads();

        // ---- Stage 2: ef = H1@ow2, v = V@vw2 (+ V2@vw2 for LP), fused epilogue ----
        {
            const int mt = tid & 31;      // lane = m → coalesced row writes
            const int ht = tid >> 5;
            const int h0 = 4 * ht;
            const int m0 = mt, m1 = mt + 32;
            float ef0[4] = {0,0,0,0}, ef1[4] = {0,0,0,0};
            float va0[4] = {0,0,0,0}, va1[4] = {0,0,0,0};
            float vc0[4] = {0,0,0,0}, vc1[4] = {0,0,0,0};

            for (int k = 0; k < KDIM; k += 4) {
                float4 g0 = *reinterpret_cast<float4*>(sm + OFF_G  + m0 * PITCH + k);
                float4 g1 = *reinterpret_cast<float4*>(sm + OFF_G  + m1 * PITCH + k);
                float4 p0 = *reinterpret_cast<float4*>(sm + OFF_V1 + m0 * PITCH + k);
                float4 p1 = *reinterpret_cast<float4*>(sm + OFF_V1 + m1 * PITCH + k);
                float4 q0, q1;
                if (isLP) {
                    q0 = *reinterpret_cast<float4*>(sm + OFF_V2 + m0 * PITCH + k);
                    q1 = *reinterpret_cast<float4*>(sm + OFF_V2 + m1 * PITCH + k);
                }
                const float* gp0 = reinterpret_cast<const float*>(&g0);
                const float* gp1 = reinterpret_cast<const float*>(&g1);
                const float* pp0 = reinterpret_cast<const float*>(&p0);
                const float* pp1 = reinterpret_cast<const float*>(&p1);
                const float* qp0 = reinterpret_cast<const float*>(&q0);
                const float* qp1 = reinterpret_cast<const float*>(&q1);
                #pragma unroll
                for (int kk = 0; kk < 4; kk++) {
                    float4 wo = *reinterpret_cast<float4*>(sm + OFF_OW2 + (k + kk) * HDIM + h0);
                    float4 wv = *reinterpret_cast<float4*>(sm + OFF_VW2 + (k + kk) * HDIM + h0);
                    const float* wop = reinterpret_cast<const float*>(&wo);
                    const float* wvp = reinterpret_cast<const float*>(&wv);
                    #pragma unroll
                    for (int c = 0; c < 4; c++) {
                        ef0[c] += gp0[kk] * wop[c];
                        ef1[c] += gp1[kk] * wop[c];
                        va0[c] += pp0[kk] * wvp[c];
                        va1[c] += pp1[kk] * wvp[c];
                    }
                    if (isLP) {
                        #pragma unroll
                        for (int c = 0; c < 4; c++) {
                            vc0[c] += qp0[kk] * wvp[c];
                            vc1[c] += qp1[kk] * wvp[c];
                        }
                    }
                }
            }

            #pragma unroll
            for (int c = 0; c < 4; c++) {
                int h = h0 + c;
                float bb = sm[OFF_B2 + h];
                size_t rb = (((size_t)(b * HDIM + h)) * NTOT + rowi) * NTOT + j0;
                out[rb + m0] = ef0[c] + va0[c] + bb;
                out[rb + m1] = ef1[c] + va1[c] + bb;
                if (isLP) {
                    // transposed slab: out[b,h, l, L+p] = ef_lp + MLP(-dlm)
                    size_t cb0 = (((size_t)(b * HDIM + h)) * NTOT + (j0 + m0)) * NTOT + rowi;
                    size_t cb1 = (((size_t)(b * HDIM + h)) * NTOT + (j0 + m1)) * NTOT + rowi;
                    out[cb0] = ef0[c] + vc0[c] + bb;
                    out[cb1] = ef1[c] + vc1[c] + bb;
                }
            }
        }
        // next-iteration __syncthreads() (after metadata) orders buffer reuse
    }
}

extern "C" void kernel_launch(void* const* d_in, const int* in_sizes, int n_in,
                              void* d_out, int out_size) {
    const float* pos    = (const float*)d_in[0];
    const int*   etype  = (const int*)d_in[1];
    // d_in[2] = protein_length (constant 768, hardcoded)
    const float* means  = (const float*)d_in[3];
    const float* stds   = (const float*)d_in[4];
    const float* mul_w  = (const float*)d_in[5];
    const float* bias_w = (const float*)d_in[6];
    const float* ow1    = (const float*)d_in[7];
    const float* ob1    = (const float*)d_in[8];
    const float* ow2    = (const float*)d_in[9];
    const float* ob2    = (const float*)d_in[10];
    const float* vw1    = (const float*)d_in[11];
    const float* vb1    = (const float*)d_in[12];
    const float* vw2    = (const float*)d_in[13];
    const float* vb2    = (const float*)d_in[14];
    float* out = (float*)d_out;

    static bool attr_set = false;
    cudaFuncSetAttribute(fused_distbias_kernel,
                         cudaFuncAttributeMaxDynamicSharedMemorySize, SMEM_BYTES);
    (void)attr_set;

    // zero the protein-protein quadrant
    {
        size_t total = (size_t)BDIM * HDIM * PLEN * (PLEN / 4);
        int grid = (int)((total + 255) / 256);
        zero_pp_kernel<<<grid, 256>>>(out);
    }

    // fused main kernel, persistent blocks (1 CTA/SM due to smem)
    fused_distbias_kernel<<<304, 256, SMEM_BYTES>>>(
        pos, etype, mul_w, bias_w, means, stds,
        ow1, ob1, ow2, ob2, vw1, vb1, vw2, vb2, out);
}

// round 3
// speedup vs baseline: 1.0498x; 1.0498x over previous
#include <cuda_runtime.h>
#include <math.h>

// Problem dims (fixed by setup_inputs)
#define BDIM 2
#define NTOT 1024
#define PLEN 768
#define LLEN 256
#define KDIM 128
#define HDIM 32

constexpr int TM    = 64;    // edges per tile
constexpr int PITCH = 132;   // smem row pitch (floats): 528B, 16B-aligned, conflict-free
constexpr int NT_LL = BDIM * LLEN * (LLEN / TM);   // 2048
constexpr int NT_LP = BDIM * PLEN * (LLEN / TM);   // 6144
constexpr int NTILES = NT_LL + NT_LP;              // 8192

// shared memory layout (float offsets)
// ow1 staged k-pair interleaved: OW1S[kp][c] = {ow1[2kp][c], ow1[2kp+1][c]}  (64x128 float2)
// ow2/vw2 staged k-pair interleaved: [kp][h] float2 (64x32 float2)
constexpr int OFF_OW1  = 0;                        // 16384 floats
constexpr int OFF_OW2  = OFF_OW1 + 64 * 128 * 2;   // 16384
constexpr int OFF_VW2  = OFF_OW2 + 64 * 32 * 2;    // 20480
constexpr int OFF_VW1  = OFF_VW2 + 64 * 32 * 2;    // 24576
constexpr int OFF_VB1  = OFF_VW1 + 3 * KDIM;       // 24960
constexpr int OFF_OB1  = OFF_VB1 + KDIM;           // 25088
constexpr int OFF_MEAN = OFF_OB1 + KDIM;           // 25216
constexpr int OFF_ISTD = OFF_MEAN + KDIM;          // 25344
constexpr int OFF_COEF = OFF_ISTD + KDIM;          // 25472
constexpr int OFF_B2   = OFF_COEF + KDIM;          // 25600
constexpr int OFF_X0   = OFF_B2 + HDIM;            // 25632
constexpr int OFF_DLM  = OFF_X0 + TM;              // 25696
constexpr int OFF_G    = OFF_DLM + TM * 3;         // 25888  [64][132], reused as H1
constexpr int OFF_V1   = OFF_G + TM * PITCH;       // 34336
constexpr int OFF_V2   = OFF_V1 + TM * PITCH;      // 42784
constexpr int SMEM_FLOATS = OFF_V2 + TM * PITCH;   // 51232
constexpr int SMEM_BYTES  = SMEM_FLOATS * 4;       // 204928

typedef unsigned long long ull;

__device__ __forceinline__ void lds_b128(ull &a, ull &b, unsigned addr) {
    asm volatile("ld.shared.v2.b64 {%0,%1},[%2];" : "=l"(a), "=l"(b) : "r"(addr));
}
__device__ __forceinline__ ull lds_b64(unsigned addr) {
    ull r; asm volatile("ld.shared.b64 %0,[%1];" : "=l"(r) : "r"(addr)); return r;
}
__device__ __forceinline__ ull ffma2(ull a, ull b, ull c) {
    ull d; asm("fma.rn.f32x2 %0,%1,%2,%3;" : "=l"(d) : "l"(a), "l"(b), "l"(c)); return d;
}
__device__ __forceinline__ float2 u2f2(ull v) {
    float2 f; asm("mov.b64 {%0,%1},%2;" : "=f"(f.x), "=f"(f.y) : "l"(v)); return f;
}

__device__ __forceinline__ float gelu_exact(float x) {
    return 0.5f * x * (1.0f + erff(x * 0.70710678118654752f));
}

// Zero-fill the protein-protein quadrant: out[b,h,i>=L,j>=L]
__global__ void zero_pp_kernel(float* __restrict__ out) {
    const int q = PLEN / 4;
    size_t idx = (size_t)blockIdx.x * blockDim.x + threadIdx.x;
    size_t total = (size_t)BDIM * HDIM * PLEN * q;
    if (idx >= total) return;
    int jq = (int)(idx % q);
    size_t r = idx / q;
    int ip = (int)(r % PLEN);
    size_t bh = r / PLEN;
    size_t addr = (bh * NTOT + (LLEN + ip)) * NTOT + LLEN + 4 * jq;
    *reinterpret_cast<float4*>(out + addr) = make_float4(0.f, 0.f, 0.f, 0.f);
}

__global__ __launch_bounds__(512, 1)
void fused_distbias_kernel(
    const float* __restrict__ pos,
    const int*   __restrict__ etype,
    const float* __restrict__ mw,
    const float* __restrict__ bw,
    const float* __restrict__ means,
    const float* __restrict__ stds,
    const float* __restrict__ ow1,
    const float* __restrict__ ob1,
    const float* __restrict__ ow2,
    const float* __restrict__ ob2,
    const float* __restrict__ vw1,
    const float* __restrict__ vb1,
    const float* __restrict__ vw2,
    const float* __restrict__ vb2,
    float* __restrict__ out)
{
    extern __shared__ float sm[];
    const int tid = threadIdx.x;
    const unsigned smb = (unsigned)__cvta_generic_to_shared(sm);

    // ---- Stage weights into shared memory, k-pair interleaved ----
    for (int i = tid; i < 64 * 128; i += 512) {
        int kp = i >> 7, c = i & 127;
        sm[OFF_OW1 + kp * 256 + 2 * c]     = ow1[(2 * kp) * KDIM + c];
        sm[OFF_OW1 + kp * 256 + 2 * c + 1] = ow1[(2 * kp + 1) * KDIM + c];
    }
    for (int i = tid; i < 64 * 32; i += 512) {
        int kp = i >> 5, h = i & 31;
        sm[OFF_OW2 + kp * 64 + 2 * h]     = ow2[(2 * kp) * HDIM + h];
        sm[OFF_OW2 + kp * 64 + 2 * h + 1] = ow2[(2 * kp + 1) * HDIM + h];
        sm[OFF_VW2 + kp * 64 + 2 * h]     = vw2[(2 * kp) * HDIM + h];
        sm[OFF_VW2 + kp * 64 + 2 * h + 1] = vw2[(2 * kp + 1) * HDIM + h];
    }
    for (int i = tid; i < 3 * KDIM; i += 512) sm[OFF_VW1 + i] = vw1[i];
    for (int i = tid; i < KDIM; i += 512) {
        sm[OFF_VB1 + i] = vb1[i];
        sm[OFF_OB1 + i] = ob1[i];
        float s  = fabsf(stds[i]) + 1e-5f;
        float is = 1.0f / s;
        sm[OFF_MEAN + i] = means[i];
        sm[OFF_ISTD + i] = is;
        sm[OFF_COEF + i] = is * (1.0f / sqrtf(2.0f * 3.14159f));
    }
    if (tid < HDIM) sm[OFF_B2 + tid] = ob2[tid] + vb2[tid];
    __syncthreads();

    for (int t = blockIdx.x; t < NTILES; t += gridDim.x) {
        int b, rowi, j0, isLP;
        if (t < NT_LL) {
            isLP = 0;
            b = t >> 10;
            int r = t & 1023;
            rowi = r >> 2;
            j0 = (r & 3) << 6;
        } else {
            isLP = 1;
            int u = t - NT_LL;
            b = u / 3072;
            int r = u % 3072;
            rowi = LLEN + (r >> 2);
            j0 = (r & 3) << 6;
        }

        // ---- Edge metadata ----
        if (tid < TM) {
            int j = j0 + tid;
            const float* pj = pos + ((size_t)b * NTOT + j) * 3;
            const float* pi = pos + ((size_t)b * NTOT + rowi) * 3;
            float d0 = pj[0] - pi[0];
            float d1 = pj[1] - pi[1];
            float d2 = pj[2] - pi[2];
            float d = 1.0f / (d0 * d0 + d1 * d1 + d2 * d2 + 1.0f);
            int e = etype[((size_t)b * NTOT + rowi) * NTOT + j];
            sm[OFF_X0 + tid] = mw[e] * d + bw[e];
            sm[OFF_DLM + tid * 3 + 0] = d0;
            sm[OFF_DLM + tid * 3 + 1] = d1;
            sm[OFF_DLM + tid * 3 + 2] = d2;
        }
        __syncthreads();

        // ---- Gaussian features + vector-MLP hidden layer(s) ----
        for (int idx = tid; idx < TM * KDIM; idx += 512) {
            int m = idx >> 7, k = idx & 127;
            float tt = (sm[OFF_X0 + m] - sm[OFF_MEAN + k]) * sm[OFF_ISTD + k];
            sm[OFF_G + m * PITCH + k] = __expf(-0.5f * tt * tt) * sm[OFF_COEF + k];
            float s = sm[OFF_DLM + m * 3 + 0] * sm[OFF_VW1 + k]
                    + sm[OFF_DLM + m * 3 + 1] * sm[OFF_VW1 + KDIM + k]
                    + sm[OFF_DLM + m * 3 + 2] * sm[OFF_VW1 + 2 * KDIM + k]
                    + sm[OFF_VB1 + k];
            sm[OFF_V1 + m * PITCH + k] = gelu_exact(s);
            if (isLP)
                sm[OFF_V2 + m * PITCH + k] = gelu_exact(2.0f * sm[OFF_VB1 + k] - s);
        }
        __syncthreads();

        // ---- Stage 1: H1 = gelu(G[64,128] @ ow1 + ob1), FFMA2 over k-pairs ----
        {
            const int nt = tid & 63;              // col pair: cols 2nt, 2nt+1 (lane-varying)
            const int mt = tid >> 6;              // row group: rows 8mt..8mt+7 (warp-uniform)
            const unsigned wbase = smb + OFF_OW1 * 4 + nt * 16;
            const unsigned gbase = smb + OFF_G * 4 + (mt * 8) * (PITCH * 4);
            ull acc[8][2];
            #pragma unroll
            for (int r = 0; r < 8; r++) { acc[r][0] = 0ull; acc[r][1] = 0ull; }

            #pragma unroll 4
            for (int kp = 0; kp < 64; kp++) {
                ull wa, wb;
                lds_b128(wa, wb, wbase + kp * 1024);   // {w[2kp][2nt],w[2kp+1][2nt]}, col 2nt+1
                #pragma unroll
                for (int r = 0; r < 8; r++) {
                    ull g = lds_b64(gbase + r * (PITCH * 4) + kp * 8);  // broadcast {g_k,g_k+1}
                    acc[r][0] = ffma2(g, wa, acc[r][0]);
                    acc[r][1] = ffma2(g, wb, acc[r][1]);
                }
            }
            __syncthreads();  // all G reads done before overwrite with H1
            float2 ob = *reinterpret_cast<const float2*>(sm + OFF_OB1 + 2 * nt);
            #pragma unroll
            for (int r = 0; r < 8; r++) {
                float2 a0 = u2f2(acc[r][0]), a1 = u2f2(acc[r][1]);
                float2 o;
                o.x = gelu_exact(a0.x + a0.y + ob.x);
                o.y = gelu_exact(a1.x + a1.y + ob.y);
                *reinterpret_cast<float2*>(sm + OFF_G + (mt * 8 + r) * PITCH + 2 * nt) = o;
            }
        }
        __syncthreads();

        // ---- Stage 2: ef = H1@ow2, va = V1@vw2 (+ vc = V2@vw2), even/odd-k split ----
        {
            const int mt = tid & 63;              // m (lane-varying: coalesced / conflict-free)
            const int ht = tid >> 6;              // h group (warp-uniform: weight broadcast)
            const int h0 = 4 * ht;
            const unsigned gA  = smb + OFF_G  * 4 + mt * (PITCH * 4);
            const unsigned pA  = smb + OFF_V1 * 4 + mt * (PITCH * 4);
            const unsigned qA  = smb + OFF_V2 * 4 + mt * (PITCH * 4);
            const unsigned woA = smb + OFF_OW2 * 4 + h0 * 8;
            const unsigned wvA = smb + OFF_VW2 * 4 + h0 * 8;
            ull ef[4] = {0,0,0,0}, va[4] = {0,0,0,0}, vc[4] = {0,0,0,0};

            if (!isLP) {
                for (int it = 0; it < 32; it++) {   // 4 k per iter (2 k-pairs)
                    ull g0, g1, p0, p1;
                    lds_b128(g0, g1, gA + it * 16);
                    lds_b128(p0, p1, pA + it * 16);
                    ull a00,a01,a02,a03, a10,a11,a12,a13;
                    lds_b128(a00, a01, woA + it * 512);
                    lds_b128(a02, a03, woA + it * 512 + 16);
                    lds_b128(a10, a11, woA + it * 512 + 256);
                    lds_b128(a12, a13, woA + it * 512 + 272);
                    ull b00,b01,b02,b03, b10,b11,b12,b13;
                    lds_b128(b00, b01, wvA + it * 512);
                    lds_b128(b02, b03, wvA + it * 512 + 16);
                    lds_b128(b10, b11, wvA + it * 512 + 256);
                    lds_b128(b12, b13, wvA + it * 512 + 272);
                    ef[0] = ffma2(g0, a00, ef[0]); ef[1] = ffma2(g0, a01, ef[1]);
                    ef[2] = ffma2(g0, a02, ef[2]); ef[3] = ffma2(g0, a03, ef[3]);
                    ef[0] = ffma2(g1, a10, ef[0]); ef[1] = ffma2(g1, a11, ef[1]);
                    ef[2] = ffma2(g1, a12, ef[2]); ef[3] = ffma2(g1, a13, ef[3]);
                    va[0] = ffma2(p0, b00, va[0]); va[1] = ffma2(p0, b01, va[1]);
                    va[2] = ffma2(p0, b02, va[2]); va[3] = ffma2(p0, b03, va[3]);
                    va[0] = ffma2(p1, b10, va[0]); va[1] = ffma2(p1, b11, va[1]);
                    va[2] = ffma2(p1, b12, va[2]); va[3] = ffma2(p1, b13, va[3]);
                }
            } else {
                for (int it = 0; it < 32; it++) {
                    ull g0, g1, p0, p1, q0, q1;
                    lds_b128(g0, g1, gA + it * 16);
                    lds_b128(p0, p1, pA + it * 16);
                    lds_b128(q0, q1, qA + it * 16);
                    ull a00,a01,a02,a03, a10,a11,a12,a13;
                    lds_b128(a00, a01, woA + it * 512);
                    lds_b128(a02, a03, woA + it * 512 + 16);
                    lds_b128(a10, a11, woA + it * 512 + 256);
                    lds_b128(a12, a13, woA + it * 512 + 272);
                    ull b00,b01,b02,b03, b10,b11,b12,b13;
                    lds_b128(b00, b01, wvA + it * 512);
                    lds_b128(b02, b03, wvA + it * 512 + 16);
                    lds_b128(b10, b11, wvA + it * 512 + 256);
                    lds_b128(b12, b13, wvA + it * 512 + 272);
                    ef[0] = ffma2(g0, a00, ef[0]); ef[1] = ffma2(g0, a01, ef[1]);
                    ef[2] = ffma2(g0, a02, ef[2]); ef[3] = ffma2(g0, a03, ef[3]);
                    ef[0] = ffma2(g1, a10, ef[0]); ef[1] = ffma2(g1, a11, ef[1]);
                    ef[2] = ffma2(g1, a12, ef[2]); ef[3] = ffma2(g1, a13, ef[3]);
                    va[0] = ffma2(p0, b00, va[0]); va[1] = ffma2(p0, b01, va[1]);
                    va[2] = ffma2(p0, b02, va[2]); va[3] = ffma2(p0, b03, va[3]);
                    va[0] = ffma2(p1, b10, va[0]); va[1] = ffma2(p1, b11, va[1]);
                    va[2] = ffma2(p1, b12, va[2]); va[3] = ffma2(p1, b13, va[3]);
                    vc[0] = ffma2(q0, b00, vc[0]); vc[1] = ffma2(q0, b01, vc[1]);
                    vc[2] = ffma2(q0, b02, vc[2]); vc[3] = ffma2(q0, b03, vc[3]);
                    vc[0] = ffma2(q1, b10, vc[0]); vc[1] = ffma2(q1, b11, vc[1]);
                    vc[2] = ffma2(q1, b12, vc[2]); vc[3] = ffma2(q1, b13, vc[3]);
                }
            }

            const size_t bh = (size_t)b * HDIM;
            #pragma unroll
            for (int c = 0; c < 4; c++) {
                int h = h0 + c;
                float2 e = u2f2(ef[c]);
                float2 v = u2f2(va[c]);
                float bb = sm[OFF_B2 + h];
                float efv = e.x + e.y;
                size_t rb = ((bh + h) * NTOT + rowi) * NTOT + j0 + mt;
                out[rb] = efv + v.x + v.y + bb;
                if (isLP) {
                    float2 w = u2f2(vc[c]);
                    size_t cb = ((bh + h) * NTOT + (j0 + mt)) * NTOT + rowi;
                    out[cb] = efv + w.x + w.y + bb;
                }
            }
        }
        // next-iteration __syncthreads() (after metadata) orders buffer reuse
    }
}

extern "C" void kernel_launch(void* const* d_in, const int* in_sizes, int n_in,
                              void* d_out, int out_size) {
    const float* pos    = (const float*)d_in[0];
    const int*   etype  = (const int*)d_in[1];
    const float* means  = (const float*)d_in[3];
    const float* stds   = (const float*)d_in[4];
    const float* mul_w  = (const float*)d_in[5];
    const float* bias_w = (const float*)d_in[6];
    const float* ow1    = (const float*)d_in[7];
    const float* ob1    = (const float*)d_in[8];
    const float* ow2    = (const float*)d_in[9];
    const float* ob2    = (const float*)d_in[10];
    const float* vw1    = (const float*)d_in[11];
    const float* vb1    = (const float*)d_in[12];
    const float* vw2    = (const float*)d_in[13];
    const float* vb2    = (const float*)d_in[14];
    float* out = (float*)d_out;

    cudaFuncSetAttribute(fused_distbias_kernel,
                         cudaFuncAttributeMaxDynamicSharedMemorySize, SMEM_BYTES);

    {
        size_t total = (size_t)BDIM * HDIM * PLEN * (PLEN / 4);
        int grid = (int)((total + 255) / 256);
        zero_pp_kernel<<<grid, 256>>>(out);
    }

    fused_distbias_kernel<<<148, 512, SMEM_BYTES>>>(
        pos, etype, mul_w, bias_w, means, stds,
        ow1, ob1, ow2, ob2, vw1, vb1, vw2, vb2, out);
}